// round 9
// baseline (speedup 1.0000x reference)
#include <cuda_runtime.h>
#include <cuda_bf16.h>
#include <cuda_fp16.h>
#include <cstdint>
#include <cstdio>

#define N_NODES 32768
#define N_EDGES 32768
#define ND 12
#define ED 5
#define GD 11
#define H 64
#define T_OUT 4
#define STEPS 3

// ---------------- device scratch ----------------
__device__ __half g_ewh[(size_t)N_EDGES * H * H];  // 256 MB [e][h*64+o]
__device__ float g_h0[(size_t)N_NODES * H];
__device__ float g_h1[(size_t)N_NODES * H];
__device__ __align__(256) __half g_hs[(size_t)N_NODES * 128];  // h split [hi|lo]
__device__ float g_agg[(size_t)N_NODES * H];
__device__ float g_gh[(size_t)N_NODES * 256];      // [gh(192) | hroot(64)] fp32
__device__ __align__(256) __half g_a[(size_t)N_EDGES * 128];   // rf split [hi|lo]
__device__ __align__(256) __half g_b[(size_t)4096 * 128];      // We2 split [hi|hi]
__device__ __align__(256) __half g_gB1[256 * 128]; // [Whh rows | root^T rows], dup hi
__device__ __align__(256) __half g_gB2[192 * 128]; // Wih rows, dup hi
__device__ float g_w1T[133 * 64];
__device__ float g_w2T[64 * 32];
__device__ float g_inv[N_NODES];
__device__ int   g_cnt[N_NODES];
__device__ int   g_src[N_EDGES];
__device__ int   g_dst[N_EDGES];
__device__ int   g_is64;

// ---------------- fused init ----------------
__global__ void init_kernel(const long long* ei, const float* __restrict__ Whh,
                            const float* __restrict__ root_, const float* __restrict__ Wih,
                            const float* __restrict__ Wd1, const float* __restrict__ Wd2,
                            const float* __restrict__ We2) {
    int gid = blockIdx.x * 256 + threadIdx.x;
    if (blockIdx.x == 0 && threadIdx.x < 32) {
        int l = threadIdx.x, ok = 1;
#pragma unroll
        for (int q = 0; q < 4; q++) {
            long long v = ei[l + q * 32];
            if (v < 0 || v >= N_NODES) ok = 0;
        }
        int all = __all_sync(0xffffffffu, ok);
        if (l == 0) g_is64 = all;
    }
    if (gid < N_NODES) g_cnt[gid] = 0;
    if (gid < N_NODES * H / 4) ((float4*)g_agg)[gid] = make_float4(0.f, 0.f, 0.f, 0.f);
    if (gid < 256 * 128) {
        int j = gid >> 7, kk = gid & 63;
        float v = (j < 192) ? Whh[j * 64 + kk] : root_[kk * 64 + (j - 192)];
        g_gB1[gid] = __float2half_rn(v);
    }
    if (gid < 192 * 128) {
        int j = gid >> 7, kk = gid & 63;
        g_gB2[gid] = __float2half_rn(Wih[j * 64 + kk]);
    }
    if (gid < 8512) {
        int o = gid / 133, c = gid % 133;
        g_w1T[c * 64 + o] = Wd1[gid];
    }
    if (gid < 2048) {
        int j = gid >> 6, o = gid & 63;
        g_w2T[o * 32 + j] = Wd2[gid];
    }
    if (gid < 4096 * 64) {
        int j = gid >> 6, k = gid & 63;
        __half hi = __float2half_rn(We2[gid]);
        size_t base = (size_t)j * 128;
        g_b[base + k] = hi;
        g_b[base + 64 + k] = hi;
    }
}

// ---------------- convert idx + count ----------------
__global__ void conv_count_kernel(const void* ei) {
    int i = blockIdx.x * blockDim.x + threadIdx.x;
    if (i >= N_EDGES) return;
    int s, d;
    if (g_is64) {
        const long long* p = (const long long*)ei;
        s = (int)p[i]; d = (int)p[N_EDGES + i];
    } else {
        const int* p = (const int*)ei;
        s = p[i]; d = p[N_EDGES + i];
    }
    g_src[i] = s; g_dst[i] = d;
    atomicAdd(&g_cnt[d], 1);
}

__global__ void inv_kernel() {
    int i = blockIdx.x * blockDim.x + threadIdx.x;
    if (i < N_NODES) {
        int c = g_cnt[i];
        g_inv[i] = 1.0f / (float)(c > 1 ? c : 1);
    }
}

// ---------------- h init (+ split) ----------------
__global__ void hinit_kernel(const float* __restrict__ x, const float* __restrict__ u,
                             const float* __restrict__ Wp, const float* __restrict__ bp) {
    __shared__ float sW[H * (ND + GD)];
    __shared__ float sb[H];
    __shared__ float su[GD];
    int t = threadIdx.x;
    for (int i = t; i < H * (ND + GD); i += 256) sW[i] = Wp[i];
    if (t < H) sb[t] = bp[t];
    if (t < GD) su[t] = u[t];
    __syncthreads();
    int gid = blockIdx.x * 256 + t;
    int node = gid >> 6, o = gid & 63;
    const float* xr = x + (size_t)node * ND;
    const float* w = sW + o * (ND + GD);
    float acc = sb[o];
#pragma unroll
    for (int i = 0; i < ND; i++) acc += xr[i] * w[i];
#pragma unroll
    for (int i = 0; i < GD; i++) acc += su[i] * w[ND + i];
    float v = tanhf(acc);
    g_h0[(size_t)node * H + o] = v;
    __half hi = __float2half_rn(v);
    g_hs[(size_t)node * 128 + o] = hi;
    g_hs[(size_t)node * 128 + 64 + o] = __float2half_rn(v - __half2float(hi));
}

// ---------------- rfeat + split fused ----------------
__global__ void rfeat_kernel(const float* __restrict__ ea, const float* __restrict__ We1,
                             const float* __restrict__ be1) {
    __shared__ float sW[H * ED];
    __shared__ float sb[H];
    int t = threadIdx.x;
    for (int i = t; i < H * ED; i += 256) sW[i] = We1[i];
    if (t < H) sb[t] = be1[t];
    __syncthreads();
    int gid = blockIdx.x * 256 + t;
    int e = gid >> 6, k = gid & 63;
    const float* er = ea + (size_t)e * ED;
    float acc = sb[k];
#pragma unroll
    for (int i = 0; i < ED; i++) acc += er[i] * sW[k * ED + i];
    float v = fmaxf(acc, 0.0f);
    __half hi = __float2half_rn(v);
    g_a[(size_t)e * 128 + k] = hi;
    g_a[(size_t)e * 128 + 64 + k] = __float2half_rn(v - __half2float(hi));
}

// ---------------- mma helper ----------------
__device__ __forceinline__ void mma16816(float* c, const uint32_t* a, const uint32_t* b) {
    asm volatile(
        "mma.sync.aligned.m16n8k16.row.col.f32.f16.f16.f32 "
        "{%0,%1,%2,%3}, {%4,%5,%6,%7}, {%8,%9}, {%0,%1,%2,%3};"
        : "+f"(c[0]), "+f"(c[1]), "+f"(c[2]), "+f"(c[3])
        : "r"(a[0]), "r"(a[1]), "r"(a[2]), "r"(a[3]), "r"(b[0]), "r"(b[1]));
}

// ---------------- ew GEMM ----------------
#define GEMM_SMEM (2 * 128 * 68 * 4)

__global__ __launch_bounds__(256) void ewgemm_kernel(const float* __restrict__ be2) {
    extern __shared__ uint32_t sw[];
    uint32_t* As = sw;
    uint32_t* Bs = sw + 128 * 68;
    const int t = threadIdx.x;
    const int jb = blockIdx.x * 128;
    const int eb = blockIdx.y * 128;

    {
        int row = t >> 1, half = t & 1;
        const uint4* asrc = (const uint4*)(g_a + (size_t)(eb + row) * 128) + half * 8;
        const uint4* bsrc = (const uint4*)(g_b + (size_t)(jb + row) * 128) + half * 8;
        uint4* adst = (uint4*)(As + row * 68) + half * 8;
        uint4* bdst = (uint4*)(Bs + row * 68) + half * 8;
#pragma unroll
        for (int q = 0; q < 8; q++) { adst[q] = asrc[q]; bdst[q] = bsrc[q]; }
    }
    __syncthreads();

    const int wid = t >> 5, lane = t & 31;
    const int wm = wid & 3, wn = wid >> 2;
    const int g = lane >> 2, t4 = lane & 3;

    float acc[2][8][4];
#pragma unroll
    for (int mi = 0; mi < 2; mi++)
#pragma unroll
        for (int ni = 0; ni < 8; ni++)
#pragma unroll
            for (int q = 0; q < 4; q++) acc[mi][ni][q] = 0.0f;

    const uint32_t* Aw = As + (wm * 32 + g) * 68;
    const uint32_t* Bw = Bs + (wn * 64 + g) * 68;
#pragma unroll
    for (int ks = 0; ks < 8; ks++) {
        const int idx0 = ks * 8 + t4;
        uint32_t a[2][4], b[8][2];
#pragma unroll
        for (int mi = 0; mi < 2; mi++) {
            const uint32_t* p = Aw + mi * 16 * 68;
            a[mi][0] = p[idx0];
            a[mi][1] = p[8 * 68 + idx0];
            a[mi][2] = p[idx0 + 4];
            a[mi][3] = p[8 * 68 + idx0 + 4];
        }
#pragma unroll
        for (int ni = 0; ni < 8; ni++) {
            const uint32_t* p = Bw + ni * 8 * 68;
            b[ni][0] = p[idx0];
            b[ni][1] = p[idx0 + 4];
        }
#pragma unroll
        for (int mi = 0; mi < 2; mi++)
#pragma unroll
            for (int ni = 0; ni < 8; ni++)
                mma16816(acc[mi][ni], a[mi], b[ni]);
    }

#pragma unroll
    for (int ni = 0; ni < 8; ni++) {
        int col = jb + wn * 64 + ni * 8 + 2 * t4;
        float2 bb = *(const float2*)&be2[col];
#pragma unroll
        for (int mi = 0; mi < 2; mi++) {
            int row = eb + wm * 32 + mi * 16 + g;
            __half2 v0 = __floats2half2_rn(acc[mi][ni][0] + bb.x, acc[mi][ni][1] + bb.y);
            __half2 v1 = __floats2half2_rn(acc[mi][ni][2] + bb.x, acc[mi][ni][3] + bb.y);
            *(__half2*)(g_ewh + (size_t)row * 4096 + col) = v0;
            *(__half2*)(g_ewh + (size_t)(row + 8) * 4096 + col) = v1;
        }
    }
}

// ---------------- per step: msg + scatter-add ----------------
__global__ __launch_bounds__(256) void msg_kernel(int parity) {
    const float* hin = parity ? g_h1 : g_h0;
    __shared__ float sh[8][64];
    int w = threadIdx.x >> 5, l = threadIdx.x & 31;
    int e = blockIdx.x * 8 + w;
    int s = g_src[e], d = g_dst[e];
    sh[w][l] = hin[(size_t)s * H + l];
    sh[w][l + 32] = hin[(size_t)s * H + l + 32];
    __syncwarp();
    float a0 = 0.0f, a1 = 0.0f;
    const __half2* row = (const __half2*)(g_ewh + (size_t)e * 4096) + l;
#pragma unroll 8
    for (int hh = 0; hh < 64; hh++) {
        float hv = sh[w][hh];
        float2 v = __half22float2(row[hh * 32]);
        a0 += hv * v.x;
        a1 += hv * v.y;
    }
    atomicAdd(&g_agg[(size_t)d * H + 2 * l], a0);
    atomicAdd(&g_agg[(size_t)d * H + 2 * l + 1], a1);
}

// ---------------- per step: GEMM1: gh = h_split @ gB1 -> g_gh (N x 256 fp32) ----------------
__global__ __launch_bounds__(256) void gru1_kernel() {
    extern __shared__ uint32_t sw[];
    uint32_t* As = sw;
    uint32_t* Bs = sw + 128 * 68;
    const int t = threadIdx.x;
    const int jb = blockIdx.x * 128;
    const int eb = blockIdx.y * 128;

    {
        int row = t >> 1, half = t & 1;
        const uint4* asrc = (const uint4*)(g_hs + (size_t)(eb + row) * 128) + half * 8;
        const uint4* bsrc = (const uint4*)(g_gB1 + (size_t)(jb + row) * 128) + half * 8;
        uint4* adst = (uint4*)(As + row * 68) + half * 8;
        uint4* bdst = (uint4*)(Bs + row * 68) + half * 8;
#pragma unroll
        for (int q = 0; q < 8; q++) { adst[q] = asrc[q]; bdst[q] = bsrc[q]; }
    }
    __syncthreads();

    const int wid = t >> 5, lane = t & 31;
    const int wm = wid & 3, wn = wid >> 2;
    const int g = lane >> 2, t4 = lane & 3;

    float acc[2][8][4];
#pragma unroll
    for (int mi = 0; mi < 2; mi++)
#pragma unroll
        for (int ni = 0; ni < 8; ni++)
#pragma unroll
            for (int q = 0; q < 4; q++) acc[mi][ni][q] = 0.0f;

    const uint32_t* Aw = As + (wm * 32 + g) * 68;
    const uint32_t* Bw = Bs + (wn * 64 + g) * 68;
#pragma unroll
    for (int ks = 0; ks < 8; ks++) {
        const int idx0 = ks * 8 + t4;
        uint32_t a[2][4], b[8][2];
#pragma unroll
        for (int mi = 0; mi < 2; mi++) {
            const uint32_t* p = Aw + mi * 16 * 68;
            a[mi][0] = p[idx0];
            a[mi][1] = p[8 * 68 + idx0];
            a[mi][2] = p[idx0 + 4];
            a[mi][3] = p[8 * 68 + idx0 + 4];
        }
#pragma unroll
        for (int ni = 0; ni < 8; ni++) {
            const uint32_t* p = Bw + ni * 8 * 68;
            b[ni][0] = p[idx0];
            b[ni][1] = p[idx0 + 4];
        }
#pragma unroll
        for (int mi = 0; mi < 2; mi++)
#pragma unroll
            for (int ni = 0; ni < 8; ni++)
                mma16816(acc[mi][ni], a[mi], b[ni]);
    }

#pragma unroll
    for (int ni = 0; ni < 8; ni++) {
        int col = jb + wn * 64 + ni * 8 + 2 * t4;
#pragma unroll
        for (int mi = 0; mi < 2; mi++) {
            int row = eb + wm * 32 + mi * 16 + g;
            *(float2*)(g_gh + (size_t)row * 256 + col) = make_float2(acc[mi][ni][0], acc[mi][ni][1]);
            *(float2*)(g_gh + (size_t)(row + 8) * 256 + col) = make_float2(acc[mi][ni][2], acc[mi][ni][3]);
        }
    }
}

// ---------------- per step: GEMM2 + m + gates fused ----------------
#define G2_SMEM ((25088 + 384) * 4)

__device__ __forceinline__ float sigf(float x) { return 1.0f / (1.0f + expf(-x)); }

__global__ __launch_bounds__(256) void gru2_kernel(int parity,
        const float* __restrict__ bih, const float* __restrict__ bhh,
        const float* __restrict__ conv_b) {
    const float* hin = parity ? g_h1 : g_h0;
    float* hout = parity ? g_h0 : g_h1;
    extern __shared__ uint32_t sw[];
    uint32_t* As = sw;                  // 128*68
    uint32_t* Bs = sw + 128 * 68;       // 192*68
    float* s_gi  = (float*)sw;          // 128*196 fp32 (aliases As/Bs post-mainloop)
    float* s_bih = (float*)sw + 25088;  // 192
    float* s_bhh = s_bih + 192;         // 192

    const int t = threadIdx.x;
    const int eb = blockIdx.x * 128;

    if (t < 192) { s_bih[t] = bih[t]; s_bhh[t] = bhh[t]; }

    // stage B (192 rows x 128 fp16 = 16 uint4 per row) -- FIXED: full row
    for (int i = t; i < 192 * 16; i += 256) {
        int row = i >> 4, q = i & 15;
        ((uint4*)(Bs + row * 68))[q] = ((const uint4*)(g_gB2 + (size_t)row * 128))[q];
    }
    // stage A = m split (computed from agg, hroot, cb); reset agg
    {
        int r = t >> 1, half = t & 1;
        int node = eb + r;
        float ic = g_inv[node];
        float* aggp = g_agg + (size_t)node * 64 + half * 32;
        const float* ghp = g_gh + (size_t)node * 256 + 192 + half * 32;
        const float* cbp = conv_b + half * 32;
#pragma unroll
        for (int q = 0; q < 8; q++) {
            float4 ag = *(float4*)(aggp + q * 4);
            float4 hr = *(const float4*)(ghp + q * 4);
            float4 cb4 = *(const float4*)(cbp + q * 4);
            *(float4*)(aggp + q * 4) = make_float4(0.f, 0.f, 0.f, 0.f);
            float m0 = fmaxf(ag.x * ic + hr.x + cb4.x, 0.f);
            float m1 = fmaxf(ag.y * ic + hr.y + cb4.y, 0.f);
            float m2 = fmaxf(ag.z * ic + hr.z + cb4.z, 0.f);
            float m3 = fmaxf(ag.w * ic + hr.w + cb4.w, 0.f);
            __half h0 = __float2half_rn(m0), h1 = __float2half_rn(m1);
            __half h2 = __float2half_rn(m2), h3 = __float2half_rn(m3);
            __half2 hi01 = __halves2half2(h0, h1), hi23 = __halves2half2(h2, h3);
            __half2 lo01 = __halves2half2(__float2half_rn(m0 - __half2float(h0)),
                                          __float2half_rn(m1 - __half2float(h1)));
            __half2 lo23 = __halves2half2(__float2half_rn(m2 - __half2float(h2)),
                                          __float2half_rn(m3 - __half2float(h3)));
            int base = r * 68 + half * 16 + q * 2;
            As[base]      = *(uint32_t*)&hi01;
            As[base + 1]  = *(uint32_t*)&hi23;
            As[base + 32] = *(uint32_t*)&lo01;
            As[base + 33] = *(uint32_t*)&lo23;
        }
    }
    __syncthreads();

    const int wid = t >> 5, lane = t & 31;
    const int wm = wid & 3, wn = wid >> 2;   // 4M x 2N; warp tile 32 x 96
    const int g = lane >> 2, t4 = lane & 3;

    float acc[2][12][4];
#pragma unroll
    for (int mi = 0; mi < 2; mi++)
#pragma unroll
        for (int ni = 0; ni < 12; ni++)
#pragma unroll
            for (int q = 0; q < 4; q++) acc[mi][ni][q] = 0.0f;

    const uint32_t* Aw = As + (wm * 32 + g) * 68;
    const uint32_t* Bw = Bs + (wn * 96 + g) * 68;
#pragma unroll
    for (int ks = 0; ks < 8; ks++) {
        const int idx0 = ks * 8 + t4;
        uint32_t a[2][4], b[12][2];
#pragma unroll
        for (int mi = 0; mi < 2; mi++) {
            const uint32_t* p = Aw + mi * 16 * 68;
            a[mi][0] = p[idx0];
            a[mi][1] = p[8 * 68 + idx0];
            a[mi][2] = p[idx0 + 4];
            a[mi][3] = p[8 * 68 + idx0 + 4];
        }
#pragma unroll
        for (int ni = 0; ni < 12; ni++) {
            const uint32_t* p = Bw + ni * 8 * 68;
            b[ni][0] = p[idx0];
            b[ni][1] = p[idx0 + 4];
        }
#pragma unroll
        for (int mi = 0; mi < 2; mi++)
#pragma unroll
            for (int ni = 0; ni < 12; ni++)
                mma16816(acc[mi][ni], a[mi], b[ni]);
    }
    __syncthreads();

    // acc -> s_gi [row][col], stride 196
#pragma unroll
    for (int ni = 0; ni < 12; ni++) {
        int col = wn * 96 + ni * 8 + 2 * t4;
#pragma unroll
        for (int mi = 0; mi < 2; mi++) {
            int row = wm * 32 + mi * 16 + g;
            *(float2*)(s_gi + row * 196 + col) = make_float2(acc[mi][ni][0], acc[mi][ni][1]);
            *(float2*)(s_gi + (row + 8) * 196 + col) = make_float2(acc[mi][ni][2], acc[mi][ni][3]);
        }
    }
    __syncthreads();

    // gates
    {
        int r = t >> 1, half = t & 1;
        int node = eb + r;
        const float* girow = s_gi + r * 196;
        const float* ghrow = g_gh + (size_t)node * 256;
#pragma unroll
        for (int q = 0; q < 8; q++) {
            int c = half * 32 + q * 4;
            float4 gir = *(const float4*)(girow + c);
            float4 giz = *(const float4*)(girow + 64 + c);
            float4 gin = *(const float4*)(girow + 128 + c);
            float4 ghr = *(const float4*)(ghrow + c);
            float4 ghz = *(const float4*)(ghrow + 64 + c);
            float4 ghn = *(const float4*)(ghrow + 128 + c);
            float4 hv  = *(const float4*)(hin + (size_t)node * 64 + c);
            float4 bir = *(const float4*)(s_bih + c);
            float4 biz = *(const float4*)(s_bih + 64 + c);
            float4 bin = *(const float4*)(s_bih + 128 + c);
            float4 bhr = *(const float4*)(s_bhh + c);
            float4 bhz = *(const float4*)(s_bhh + 64 + c);
            float4 bhn = *(const float4*)(s_bhh + 128 + c);
            float o_[4], lo_[4];
            float gr[4] = {gir.x + bir.x + ghr.x + bhr.x, gir.y + bir.y + ghr.y + bhr.y,
                           gir.z + bir.z + ghr.z + bhr.z, gir.w + bir.w + ghr.w + bhr.w};
            float gz[4] = {giz.x + biz.x + ghz.x + bhz.x, giz.y + biz.y + ghz.y + bhz.y,
                           giz.z + biz.z + ghz.z + bhz.z, giz.w + biz.w + ghz.w + bhz.w};
            float gn_i[4] = {gin.x + bin.x, gin.y + bin.y, gin.z + bin.z, gin.w + bin.w};
            float gn_h[4] = {ghn.x + bhn.x, ghn.y + bhn.y, ghn.z + bhn.z, ghn.w + bhn.w};
            float hvv[4] = {hv.x, hv.y, hv.z, hv.w};
#pragma unroll
            for (int j = 0; j < 4; j++) {
                float rr = sigf(gr[j]);
                float zz = sigf(gz[j]);
                float nn = tanhf(gn_i[j] + rr * gn_h[j]);
                o_[j] = (1.0f - zz) * nn + zz * hvv[j];
                __half hh = __float2half_rn(o_[j]);
                lo_[j] = o_[j] - __half2float(hh);
            }
            *(float4*)(hout + (size_t)node * 64 + c) = make_float4(o_[0], o_[1], o_[2], o_[3]);
            __half2* hsp = (__half2*)(g_hs + (size_t)node * 128 + c);
            hsp[0] = __floats2half2_rn(o_[0], o_[1]);
            hsp[1] = __floats2half2_rn(o_[2], o_[3]);
            __half2* lsp = (__half2*)(g_hs + (size_t)node * 128 + 64 + c);
            lsp[0] = __floats2half2_rn(lo_[0], lo_[1]);
            lsp[1] = __floats2half2_rn(lo_[2], lo_[3]);
        }
    }
}

// ---------------- decoder ----------------
__global__ __launch_bounds__(256) void decoder_kernel(int parity,
        const float* __restrict__ ea,
        const float* __restrict__ bd1, const float* __restrict__ bd2,
        const float* __restrict__ Wd3, const float* __restrict__ bd3,
        float* __restrict__ out) {
    const float* hin = parity ? g_h1 : g_h0;
    extern __shared__ float sm[];
    float* s_w1 = sm;
    float* s_w2 = s_w1 + 133 * 64;
    float* s_w3 = s_w2 + 64 * 32;
    float* s_b1 = s_w3 + 128;
    float* s_b2 = s_b1 + 64;
    float* s_b3 = s_b2 + 32;
    float* s_in = s_b3 + 4;
    float* s_d1 = s_in + 8 * 136;
    float* s_d2 = s_d1 + 8 * 64;

    int t = threadIdx.x;
    for (int i = t; i < 133 * 64; i += 256) s_w1[i] = g_w1T[i];
    for (int i = t; i < 64 * 32; i += 256) s_w2[i] = g_w2T[i];
    if (t < 128) s_w3[t] = Wd3[t];
    if (t < 64) s_b1[t] = bd1[t];
    if (t < 32) s_b2[t] = bd2[t];
    if (t < 4)  s_b3[t] = bd3[t];
    __syncthreads();

    int w = t >> 5, l = t & 31;

    for (int it = 0; it < 8; it++) {
        int e = blockIdx.x * 64 + it * 8 + w;
        int s = g_src[e], d = g_dst[e];
        s_in[w * 136 + l]      = hin[(size_t)s * H + l];
        s_in[w * 136 + l + 32] = hin[(size_t)s * H + l + 32];
        s_in[w * 136 + 64 + l]      = hin[(size_t)d * H + l];
        s_in[w * 136 + 64 + l + 32] = hin[(size_t)d * H + l + 32];
        if (l < ED) s_in[w * 136 + 128 + l] = ea[(size_t)e * ED + l];
        __syncwarp();

        float a0 = s_b1[l], a1 = s_b1[l + 32];
        for (int i = 0; i < 133; i++) {
            float v = s_in[w * 136 + i];
            a0 += v * s_w1[i * 64 + l];
            a1 += v * s_w1[i * 64 + l + 32];
        }
        s_d1[w * 64 + l] = fmaxf(a0, 0.0f);
        s_d1[w * 64 + l + 32] = fmaxf(a1, 0.0f);
        __syncwarp();

        float a2 = s_b2[l];
        for (int o = 0; o < 64; o++) a2 += s_d1[w * 64 + o] * s_w2[o * 32 + l];
        s_d2[w * 32 + l] = fmaxf(a2, 0.0f);
        __syncwarp();

        if (l < T_OUT) {
            float a3 = s_b3[l];
            for (int j = 0; j < 32; j++) a3 += s_d2[w * 32 + j] * s_w3[l * 32 + j];
            out[(size_t)e * T_OUT + l] = a3;
        }
        __syncwarp();
    }
}

#define DEC_SMEM  ((133*64 + 64*32 + 128 + 64 + 32 + 4 + 8*136 + 8*64 + 8*32) * 4)

static void set_attrs() {
    cudaFuncSetAttribute(ewgemm_kernel, cudaFuncAttributeMaxDynamicSharedMemorySize, GEMM_SMEM);
    cudaFuncSetAttribute(gru1_kernel, cudaFuncAttributeMaxDynamicSharedMemorySize, GEMM_SMEM);
    cudaFuncSetAttribute(gru2_kernel, cudaFuncAttributeMaxDynamicSharedMemorySize, G2_SMEM);
    cudaFuncSetAttribute(decoder_kernel, cudaFuncAttributeMaxDynamicSharedMemorySize, DEC_SMEM);
}

namespace { struct WarmLoad { WarmLoad() { set_attrs(); } } s_warm; }

extern "C" void kernel_launch(void* const* d_in, const int* in_sizes, int n_in,
                              void* d_out, int out_size) {
    (void)in_sizes; (void)n_in; (void)out_size;
    const float* x   = (const float*)d_in[0];
    const void*  ei  = d_in[1];
    const float* ea  = (const float*)d_in[2];
    const float* u   = (const float*)d_in[3];
    const float* Wp  = (const float*)d_in[4];
    const float* bp  = (const float*)d_in[5];
    const float* We1 = (const float*)d_in[6];
    const float* be1 = (const float*)d_in[7];
    const float* We2 = (const float*)d_in[8];
    const float* be2 = (const float*)d_in[9];
    const float* root = (const float*)d_in[10];
    const float* cb   = (const float*)d_in[11];
    const float* Wih = (const float*)d_in[12];
    const float* bih = (const float*)d_in[13];
    const float* Whh = (const float*)d_in[14];
    const float* bhh = (const float*)d_in[15];
    const float* Wd1 = (const float*)d_in[16];
    const float* bd1 = (const float*)d_in[17];
    const float* Wd2 = (const float*)d_in[18];
    const float* bd2 = (const float*)d_in[19];
    const float* Wd3 = (const float*)d_in[20];
    const float* bd3 = (const float*)d_in[21];
    float* out = (float*)d_out;

    set_attrs();

    init_kernel<<<N_NODES * H / 4 / 256, 256>>>((const long long*)ei, Whh, root, Wih, Wd1, Wd2, We2);
    conv_count_kernel<<<N_EDGES / 256, 256>>>(ei);
    inv_kernel<<<N_NODES / 256, 256>>>();
    hinit_kernel<<<N_NODES * H / 256, 256>>>(x, u, Wp, bp);
    rfeat_kernel<<<N_EDGES * H / 256, 256>>>(ea, We1, be1);

    {
        dim3 grid(4096 / 128, N_EDGES / 128);
        ewgemm_kernel<<<grid, 256, GEMM_SMEM>>>(be2);
    }

    for (int s = 0; s < STEPS; s++) {
        int parity = s & 1;
        msg_kernel<<<N_EDGES / 8, 256>>>(parity);
        {
            dim3 grid(2, N_NODES / 128);
            gru1_kernel<<<grid, 256, GEMM_SMEM>>>();
        }
        gru2_kernel<<<N_NODES / 128, 256, G2_SMEM>>>(parity, bih, bhh, cb);
    }

    decoder_kernel<<<N_EDGES / 64, 256, DEC_SMEM>>>(1, ea, bd1, bd2, Wd3, bd3, out);
}

// round 10
// speedup vs baseline: 1.1053x; 1.1053x over previous
#include <cuda_runtime.h>
#include <cuda_bf16.h>
#include <cuda_fp16.h>
#include <cstdint>
#include <cstdio>

#define N_NODES 32768
#define N_EDGES 32768
#define ND 12
#define ED 5
#define GD 11
#define H 64
#define T_OUT 4
#define STEPS 3

// ---------------- device scratch ----------------
__device__ __half g_ewh[(size_t)N_EDGES * H * H];  // 256 MB [e][h*64+o]
__device__ float g_h0[(size_t)N_NODES * H];
__device__ float g_h1[(size_t)N_NODES * H];
__device__ float g_agg[(size_t)N_NODES * H];
__device__ __align__(256) __half g_a[(size_t)N_EDGES * 128];   // rf split [hi|lo]
__device__ __align__(256) __half g_b[(size_t)4096 * 128];      // We2 split [hi|hi]
__device__ float g_wihT[64 * 192];  // [o][j]
__device__ float g_whhT[64 * 192];  // [o][j]
__device__ float g_w1T[133 * 64];
__device__ float g_w2T[64 * 32];
__device__ float g_inv[N_NODES];
__device__ int   g_cnt[N_NODES];
__device__ int   g_src[N_EDGES];
__device__ int   g_dst[N_EDGES];
__device__ int   g_is64;

// ---------------- fused init: detect, zero, transposes, We2 split ----------------
__global__ void init_kernel(const long long* ei, const float* __restrict__ Wih,
                            const float* __restrict__ Whh,
                            const float* __restrict__ Wd1, const float* __restrict__ Wd2,
                            const float* __restrict__ We2) {
    int gid = blockIdx.x * 256 + threadIdx.x;
    if (blockIdx.x == 0 && threadIdx.x < 32) {
        int l = threadIdx.x, ok = 1;
#pragma unroll
        for (int q = 0; q < 4; q++) {
            long long v = ei[l + q * 32];
            if (v < 0 || v >= N_NODES) ok = 0;
        }
        int all = __all_sync(0xffffffffu, ok);
        if (l == 0) g_is64 = all;
    }
    if (gid < N_NODES) g_cnt[gid] = 0;
    if (gid < N_NODES * H / 4) ((float4*)g_agg)[gid] = make_float4(0.f, 0.f, 0.f, 0.f);
    if (gid < 12288) {
        int j = gid >> 6, o = gid & 63;
        g_wihT[o * 192 + j] = Wih[gid];
        g_whhT[o * 192 + j] = Whh[gid];
    }
    if (gid < 8512) {
        int o = gid / 133, c = gid % 133;
        g_w1T[c * 64 + o] = Wd1[gid];
    }
    if (gid < 2048) {
        int j = gid >> 6, o = gid & 63;
        g_w2T[o * 32 + j] = Wd2[gid];
    }
    if (gid < 4096 * 64) {
        int j = gid >> 6, k = gid & 63;
        __half hi = __float2half_rn(We2[gid]);
        size_t base = (size_t)j * 128;
        g_b[base + k] = hi;
        g_b[base + 64 + k] = hi;
    }
}

// ---------------- convert idx + count ----------------
__global__ void conv_count_kernel(const void* ei) {
    int i = blockIdx.x * blockDim.x + threadIdx.x;
    if (i >= N_EDGES) return;
    int s, d;
    if (g_is64) {
        const long long* p = (const long long*)ei;
        s = (int)p[i]; d = (int)p[N_EDGES + i];
    } else {
        const int* p = (const int*)ei;
        s = p[i]; d = p[N_EDGES + i];
    }
    g_src[i] = s; g_dst[i] = d;
    atomicAdd(&g_cnt[d], 1);
}

__global__ void inv_kernel() {
    int i = blockIdx.x * blockDim.x + threadIdx.x;
    if (i < N_NODES) {
        int c = g_cnt[i];
        g_inv[i] = 1.0f / (float)(c > 1 ? c : 1);
    }
}

// ---------------- h init ----------------
__global__ void hinit_kernel(const float* __restrict__ x, const float* __restrict__ u,
                             const float* __restrict__ Wp, const float* __restrict__ bp) {
    __shared__ float sW[H * (ND + GD)];
    __shared__ float sb[H];
    __shared__ float su[GD];
    int t = threadIdx.x;
    for (int i = t; i < H * (ND + GD); i += 256) sW[i] = Wp[i];
    if (t < H) sb[t] = bp[t];
    if (t < GD) su[t] = u[t];
    __syncthreads();
    int gid = blockIdx.x * 256 + t;
    int node = gid >> 6, o = gid & 63;
    const float* xr = x + (size_t)node * ND;
    const float* w = sW + o * (ND + GD);
    float acc = sb[o];
#pragma unroll
    for (int i = 0; i < ND; i++) acc += xr[i] * w[i];
#pragma unroll
    for (int i = 0; i < GD; i++) acc += su[i] * w[ND + i];
    g_h0[(size_t)node * H + o] = tanhf(acc);
}

// ---------------- rfeat + split fused ----------------
__global__ void rfeat_kernel(const float* __restrict__ ea, const float* __restrict__ We1,
                             const float* __restrict__ be1) {
    __shared__ float sW[H * ED];
    __shared__ float sb[H];
    int t = threadIdx.x;
    for (int i = t; i < H * ED; i += 256) sW[i] = We1[i];
    if (t < H) sb[t] = be1[t];
    __syncthreads();
    int gid = blockIdx.x * 256 + t;
    int e = gid >> 6, k = gid & 63;
    const float* er = ea + (size_t)e * ED;
    float acc = sb[k];
#pragma unroll
    for (int i = 0; i < ED; i++) acc += er[i] * sW[k * ED + i];
    float v = fmaxf(acc, 0.0f);
    __half hi = __float2half_rn(v);
    g_a[(size_t)e * 128 + k] = hi;
    g_a[(size_t)e * 128 + 64 + k] = __float2half_rn(v - __half2float(hi));
}

// ---------------- mma helper ----------------
__device__ __forceinline__ void mma16816(float* c, const uint32_t* a, const uint32_t* b) {
    asm volatile(
        "mma.sync.aligned.m16n8k16.row.col.f32.f16.f16.f32 "
        "{%0,%1,%2,%3}, {%4,%5,%6,%7}, {%8,%9}, {%0,%1,%2,%3};"
        : "+f"(c[0]), "+f"(c[1]), "+f"(c[2]), "+f"(c[3])
        : "r"(a[0]), "r"(a[1]), "r"(a[2]), "r"(a[3]), "r"(b[0]), "r"(b[1]));
}

// ---------------- ew GEMM (verified R9 version) ----------------
#define GEMM_SMEM (2 * 128 * 68 * 4)

__global__ __launch_bounds__(256) void ewgemm_kernel(const float* __restrict__ be2) {
    extern __shared__ uint32_t sw[];
    uint32_t* As = sw;
    uint32_t* Bs = sw + 128 * 68;
    const int t = threadIdx.x;
    const int jb = blockIdx.x * 128;
    const int eb = blockIdx.y * 128;

    {
        int row = t >> 1, half = t & 1;
        const uint4* asrc = (const uint4*)(g_a + (size_t)(eb + row) * 128) + half * 8;
        const uint4* bsrc = (const uint4*)(g_b + (size_t)(jb + row) * 128) + half * 8;
        uint4* adst = (uint4*)(As + row * 68) + half * 8;
        uint4* bdst = (uint4*)(Bs + row * 68) + half * 8;
#pragma unroll
        for (int q = 0; q < 8; q++) { adst[q] = asrc[q]; bdst[q] = bsrc[q]; }
    }
    __syncthreads();

    const int wid = t >> 5, lane = t & 31;
    const int wm = wid & 3, wn = wid >> 2;
    const int g = lane >> 2, t4 = lane & 3;

    float acc[2][8][4];
#pragma unroll
    for (int mi = 0; mi < 2; mi++)
#pragma unroll
        for (int ni = 0; ni < 8; ni++)
#pragma unroll
            for (int q = 0; q < 4; q++) acc[mi][ni][q] = 0.0f;

    const uint32_t* Aw = As + (wm * 32 + g) * 68;
    const uint32_t* Bw = Bs + (wn * 64 + g) * 68;
#pragma unroll
    for (int ks = 0; ks < 8; ks++) {
        const int idx0 = ks * 8 + t4;
        uint32_t a[2][4], b[8][2];
#pragma unroll
        for (int mi = 0; mi < 2; mi++) {
            const uint32_t* p = Aw + mi * 16 * 68;
            a[mi][0] = p[idx0];
            a[mi][1] = p[8 * 68 + idx0];
            a[mi][2] = p[idx0 + 4];
            a[mi][3] = p[8 * 68 + idx0 + 4];
        }
#pragma unroll
        for (int ni = 0; ni < 8; ni++) {
            const uint32_t* p = Bw + ni * 8 * 68;
            b[ni][0] = p[idx0];
            b[ni][1] = p[idx0 + 4];
        }
#pragma unroll
        for (int mi = 0; mi < 2; mi++)
#pragma unroll
            for (int ni = 0; ni < 8; ni++)
                mma16816(acc[mi][ni], a[mi], b[ni]);
    }

#pragma unroll
    for (int ni = 0; ni < 8; ni++) {
        int col = jb + wn * 64 + ni * 8 + 2 * t4;
        float2 bb = *(const float2*)&be2[col];
#pragma unroll
        for (int mi = 0; mi < 2; mi++) {
            int row = eb + wm * 32 + mi * 16 + g;
            __half2 v0 = __floats2half2_rn(acc[mi][ni][0] + bb.x, acc[mi][ni][1] + bb.y);
            __half2 v1 = __floats2half2_rn(acc[mi][ni][2] + bb.x, acc[mi][ni][3] + bb.y);
            *(__half2*)(g_ewh + (size_t)row * 4096 + col) = v0;
            *(__half2*)(g_ewh + (size_t)(row + 8) * 4096 + col) = v1;
        }
    }
}

// ---------------- per step: msg + scatter-add (16 edges/block, unroll 16) ----------------
__global__ __launch_bounds__(512) void msg_kernel(int parity) {
    const float* hin = parity ? g_h1 : g_h0;
    __shared__ float sh[16][64];
    int w = threadIdx.x >> 5, l = threadIdx.x & 31;
    int e = blockIdx.x * 16 + w;
    int s = g_src[e], d = g_dst[e];
    sh[w][l] = hin[(size_t)s * H + l];
    sh[w][l + 32] = hin[(size_t)s * H + l + 32];
    __syncwarp();
    float a0 = 0.0f, a1 = 0.0f;
    const __half2* row = (const __half2*)(g_ewh + (size_t)e * 4096) + l;
#pragma unroll 16
    for (int hh = 0; hh < 64; hh++) {
        float hv = sh[w][hh];
        float2 v = __half22float2(row[hh * 32]);
        a0 += hv * v.x;
        a1 += hv * v.y;
    }
    atomicAdd(&g_agg[(size_t)d * H + 2 * l], a0);
    atomicAdd(&g_agg[(size_t)d * H + 2 * l + 1], a1);
}

// ---------------- per step: scalar GRU, 128 blocks x 4 chunks of 64 nodes ----------------
#define GRU_SMEM  ((4096 + 12288 + 12288 + 64 + 192 + 192 + 4096 + 4096) * 4)

__global__ __launch_bounds__(512) void gru_kernel(int parity,
        const float* __restrict__ root, const float* __restrict__ conv_b,
        const float* __restrict__ bih, const float* __restrict__ bhh) {
    const float* hin = parity ? g_h1 : g_h0;
    float* hout = parity ? g_h0 : g_h1;
    extern __shared__ float sm[];
    float* s_root = sm;                 // 4096 [h][o]
    float* s_wih = s_root + 4096;       // 12288 [o][j] pre-transposed
    float* s_whh = s_wih + 12288;
    float* s_cb  = s_whh + 12288;
    float* s_bih = s_cb + 64;
    float* s_bhh = s_bih + 192;
    float* s_h   = s_bhh + 192;
    float* s_m   = s_h + 4096;

    int t = threadIdx.x;
    for (int i = t; i < 4096; i += 512) s_root[i] = root[i];
    for (int i = t; i < 12288; i += 512) {
        s_wih[i] = g_wihT[i];
        s_whh[i] = g_whhT[i];
    }
    if (t < 64) s_cb[t] = conv_b[t];
    if (t < 192) { s_bih[t] = bih[t]; s_bhh[t] = bhh[t]; }
    __syncthreads();

    int w = t >> 5, l = t & 31;

    for (int c = 0; c < 4; c++) {
        int nb = blockIdx.x * 256 + c * 64 + w * 4;
#pragma unroll
        for (int i = 0; i < 4; i++) {
            s_h[(w * 4 + i) * 64 + l] = hin[(size_t)(nb + i) * H + l];
            s_h[(w * 4 + i) * 64 + l + 32] = hin[(size_t)(nb + i) * H + l + 32];
        }
        __syncwarp();

        float accm0[4] = {0, 0, 0, 0}, accm1[4] = {0, 0, 0, 0};
        for (int hh = 0; hh < 64; hh++) {
            float r0 = s_root[hh * 64 + l];
            float r1 = s_root[hh * 64 + l + 32];
#pragma unroll
            for (int i = 0; i < 4; i++) {
                float hv = s_h[(w * 4 + i) * 64 + hh];
                accm0[i] += hv * r0;
                accm1[i] += hv * r1;
            }
        }
#pragma unroll
        for (int i = 0; i < 4; i++) {
            float ic = g_inv[nb + i];
            size_t i0 = (size_t)(nb + i) * H + l;
            size_t i1 = i0 + 32;
            float ag0 = g_agg[i0], ag1 = g_agg[i1];
            g_agg[i0] = 0.0f; g_agg[i1] = 0.0f;
            float m0 = fmaxf(ag0 * ic + accm0[i] + s_cb[l], 0.0f);
            float m1 = fmaxf(ag1 * ic + accm1[i] + s_cb[l + 32], 0.0f);
            s_m[(w * 4 + i) * 64 + l] = m0;
            s_m[(w * 4 + i) * 64 + l + 32] = m1;
        }
        __syncwarp();

        float gi[4][6];
#pragma unroll
        for (int i = 0; i < 4; i++)
#pragma unroll
            for (int jj = 0; jj < 6; jj++) gi[i][jj] = 0.0f;
        for (int o = 0; o < 64; o++) {
            float wv[6];
#pragma unroll
            for (int jj = 0; jj < 6; jj++) wv[jj] = s_wih[o * 192 + l + 32 * jj];
#pragma unroll
            for (int i = 0; i < 4; i++) {
                float mv = s_m[(w * 4 + i) * 64 + o];
#pragma unroll
                for (int jj = 0; jj < 6; jj++) gi[i][jj] += mv * wv[jj];
            }
        }
        float gh[4][6];
#pragma unroll
        for (int i = 0; i < 4; i++)
#pragma unroll
            for (int jj = 0; jj < 6; jj++) gh[i][jj] = 0.0f;
        for (int o = 0; o < 64; o++) {
            float wv[6];
#pragma unroll
            for (int jj = 0; jj < 6; jj++) wv[jj] = s_whh[o * 192 + l + 32 * jj];
#pragma unroll
            for (int i = 0; i < 4; i++) {
                float hv = s_h[(w * 4 + i) * 64 + o];
#pragma unroll
                for (int jj = 0; jj < 6; jj++) gh[i][jj] += hv * wv[jj];
            }
        }
#pragma unroll
        for (int i = 0; i < 4; i++) {
#pragma unroll
            for (int half = 0; half < 2; half++) {
                int o = l + 32 * half;
                float gir = gi[i][half]     + s_bih[o];
                float ghr = gh[i][half]     + s_bhh[o];
                float giz = gi[i][2 + half] + s_bih[64 + o];
                float ghz = gh[i][2 + half] + s_bhh[64 + o];
                float gin = gi[i][4 + half] + s_bih[128 + o];
                float ghn = gh[i][4 + half] + s_bhh[128 + o];
                float r = 1.0f / (1.0f + expf(-(gir + ghr)));
                float z = 1.0f / (1.0f + expf(-(giz + ghz)));
                float ng = tanhf(gin + r * ghn);
                float hp = s_h[(w * 4 + i) * 64 + o];
                hout[(size_t)(nb + i) * H + o] = (1.0f - z) * ng + z * hp;
            }
        }
        __syncwarp();
    }
}

// ---------------- decoder: 512 blocks x 8 iters x 8 edges ----------------
__global__ __launch_bounds__(256) void decoder_kernel(int parity,
        const float* __restrict__ ea,
        const float* __restrict__ bd1, const float* __restrict__ bd2,
        const float* __restrict__ Wd3, const float* __restrict__ bd3,
        float* __restrict__ out) {
    const float* hin = parity ? g_h1 : g_h0;
    extern __shared__ float sm[];
    float* s_w1 = sm;
    float* s_w2 = s_w1 + 133 * 64;
    float* s_w3 = s_w2 + 64 * 32;
    float* s_b1 = s_w3 + 128;
    float* s_b2 = s_b1 + 64;
    float* s_b3 = s_b2 + 32;
    float* s_in = s_b3 + 4;
    float* s_d1 = s_in + 8 * 136;
    float* s_d2 = s_d1 + 8 * 64;

    int t = threadIdx.x;
    for (int i = t; i < 133 * 64; i += 256) s_w1[i] = g_w1T[i];
    for (int i = t; i < 64 * 32; i += 256) s_w2[i] = g_w2T[i];
    if (t < 128) s_w3[t] = Wd3[t];
    if (t < 64) s_b1[t] = bd1[t];
    if (t < 32) s_b2[t] = bd2[t];
    if (t < 4)  s_b3[t] = bd3[t];
    __syncthreads();

    int w = t >> 5, l = t & 31;

    for (int it = 0; it < 8; it++) {
        int e = blockIdx.x * 64 + it * 8 + w;
        int s = g_src[e], d = g_dst[e];
        s_in[w * 136 + l]      = hin[(size_t)s * H + l];
        s_in[w * 136 + l + 32] = hin[(size_t)s * H + l + 32];
        s_in[w * 136 + 64 + l]      = hin[(size_t)d * H + l];
        s_in[w * 136 + 64 + l + 32] = hin[(size_t)d * H + l + 32];
        if (l < ED) s_in[w * 136 + 128 + l] = ea[(size_t)e * ED + l];
        __syncwarp();

        float a0 = s_b1[l], a1 = s_b1[l + 32];
        for (int i = 0; i < 133; i++) {
            float v = s_in[w * 136 + i];
            a0 += v * s_w1[i * 64 + l];
            a1 += v * s_w1[i * 64 + l + 32];
        }
        s_d1[w * 64 + l] = fmaxf(a0, 0.0f);
        s_d1[w * 64 + l + 32] = fmaxf(a1, 0.0f);
        __syncwarp();

        float a2 = s_b2[l];
        for (int o = 0; o < 64; o++) a2 += s_d1[w * 64 + o] * s_w2[o * 32 + l];
        s_d2[w * 32 + l] = fmaxf(a2, 0.0f);
        __syncwarp();

        if (l < T_OUT) {
            float a3 = s_b3[l];
            for (int j = 0; j < 32; j++) a3 += s_d2[w * 32 + j] * s_w3[l * 32 + j];
            out[(size_t)e * T_OUT + l] = a3;
        }
        __syncwarp();
    }
}

#define DEC_SMEM  ((133*64 + 64*32 + 128 + 64 + 32 + 4 + 8*136 + 8*64 + 8*32) * 4)

static void set_attrs() {
    cudaFuncSetAttribute(ewgemm_kernel, cudaFuncAttributeMaxDynamicSharedMemorySize, GEMM_SMEM);
    cudaFuncSetAttribute(gru_kernel, cudaFuncAttributeMaxDynamicSharedMemorySize, GRU_SMEM);
    cudaFuncSetAttribute(decoder_kernel, cudaFuncAttributeMaxDynamicSharedMemorySize, DEC_SMEM);
}

namespace { struct WarmLoad { WarmLoad() { set_attrs(); } } s_warm; }

extern "C" void kernel_launch(void* const* d_in, const int* in_sizes, int n_in,
                              void* d_out, int out_size) {
    (void)in_sizes; (void)n_in; (void)out_size;
    const float* x   = (const float*)d_in[0];
    const void*  ei  = d_in[1];
    const float* ea  = (const float*)d_in[2];
    const float* u   = (const float*)d_in[3];
    const float* Wp  = (const float*)d_in[4];
    const float* bp  = (const float*)d_in[5];
    const float* We1 = (const float*)d_in[6];
    const float* be1 = (const float*)d_in[7];
    const float* We2 = (const float*)d_in[8];
    const float* be2 = (const float*)d_in[9];
    const float* root = (const float*)d_in[10];
    const float* cb   = (const float*)d_in[11];
    const float* Wih = (const float*)d_in[12];
    const float* bih = (const float*)d_in[13];
    const float* Whh = (const float*)d_in[14];
    const float* bhh = (const float*)d_in[15];
    const float* Wd1 = (const float*)d_in[16];
    const float* bd1 = (const float*)d_in[17];
    const float* Wd2 = (const float*)d_in[18];
    const float* bd2 = (const float*)d_in[19];
    const float* Wd3 = (const float*)d_in[20];
    const float* bd3 = (const float*)d_in[21];
    float* out = (float*)d_out;

    set_attrs();

    init_kernel<<<N_NODES * H / 4 / 256, 256>>>((const long long*)ei, Wih, Whh, Wd1, Wd2, We2);
    conv_count_kernel<<<N_EDGES / 256, 256>>>(ei);
    inv_kernel<<<N_NODES / 256, 256>>>();
    hinit_kernel<<<N_NODES * H / 256, 256>>>(x, u, Wp, bp);
    rfeat_kernel<<<N_EDGES * H / 256, 256>>>(ea, We1, be1);

    {
        dim3 grid(4096 / 128, N_EDGES / 128);
        ewgemm_kernel<<<grid, 256, GEMM_SMEM>>>(be2);
    }

    for (int s = 0; s < STEPS; s++) {
        int parity = s & 1;
        msg_kernel<<<N_EDGES / 16, 512>>>(parity);
        gru_kernel<<<N_NODES / 256, 512, GRU_SMEM>>>(parity, root, cb, bih, bhh);
    }

    decoder_kernel<<<N_EDGES / 64, 256, DEC_SMEM>>>(1, ea, bd1, bd2, Wd3, bd3, out);
}

// round 12
// speedup vs baseline: 1.2618x; 1.1416x over previous
#include <cuda_runtime.h>
#include <cuda_bf16.h>
#include <cuda_fp16.h>
#include <cstdint>
#include <cstdio>

#define N_NODES 32768
#define N_EDGES 32768
#define ND 12
#define ED 5
#define GD 11
#define H 64
#define T_OUT 4
#define STEPS 3

// ---------------- device scratch ----------------
__device__ __half g_ewh[(size_t)N_EDGES * H * H];  // 256 MB [e][h*64+o]
__device__ float g_h0[(size_t)N_NODES * H];
__device__ float g_h1[(size_t)N_NODES * H];
__device__ __align__(256) __half g_hs[(size_t)N_NODES * 128];  // h split [hi|lo]
__device__ float g_agg[(size_t)N_NODES * H];
__device__ __align__(256) __half g_a[(size_t)N_EDGES * 128];   // rf split [hi|lo]
__device__ __align__(256) __half g_b[(size_t)4096 * 128];      // We2 split [hi|hi]
__device__ __align__(256) __half g_gB1[256 * 128]; // [Whh rows | root^T rows], dup hi
__device__ __align__(256) __half g_gB2[192 * 128]; // Wih rows, dup hi
__device__ float g_w1T[133 * 64];
__device__ float g_w2T[64 * 32];
__device__ float g_inv[N_NODES];
__device__ int   g_cnt[N_NODES];
__device__ int   g_src[N_EDGES];
__device__ int   g_dst[N_EDGES];
__device__ int   g_is64;

// ---------------- fused init ----------------
__global__ void init_kernel(const long long* ei, const float* __restrict__ Whh,
                            const float* __restrict__ root_, const float* __restrict__ Wih,
                            const float* __restrict__ Wd1, const float* __restrict__ Wd2,
                            const float* __restrict__ We2) {
    int gid = blockIdx.x * 256 + threadIdx.x;
    if (blockIdx.x == 0 && threadIdx.x < 32) {
        int l = threadIdx.x, ok = 1;
#pragma unroll
        for (int q = 0; q < 4; q++) {
            long long v = ei[l + q * 32];
            if (v < 0 || v >= N_NODES) ok = 0;
        }
        int all = __all_sync(0xffffffffu, ok);
        if (l == 0) g_is64 = all;
    }
    if (gid < N_NODES) g_cnt[gid] = 0;
    if (gid < N_NODES * H / 4) ((float4*)g_agg)[gid] = make_float4(0.f, 0.f, 0.f, 0.f);
    if (gid < 256 * 128) {
        int j = gid >> 7, kk = gid & 63;   // hi duplication across halves
        float v = (j < 192) ? Whh[j * 64 + kk] : root_[kk * 64 + (j - 192)];
        g_gB1[gid] = __float2half_rn(v);
    }
    if (gid < 192 * 128) {
        int j = gid >> 7, kk = gid & 63;
        g_gB2[gid] = __float2half_rn(Wih[j * 64 + kk]);
    }
    if (gid < 8512) {
        int o = gid / 133, c = gid % 133;
        g_w1T[c * 64 + o] = Wd1[gid];
    }
    if (gid < 2048) {
        int j = gid >> 6, o = gid & 63;
        g_w2T[o * 32 + j] = Wd2[gid];
    }
    if (gid < 4096 * 64) {
        int j = gid >> 6, k = gid & 63;
        __half hi = __float2half_rn(We2[gid]);
        size_t base = (size_t)j * 128;
        g_b[base + k] = hi;
        g_b[base + 64 + k] = hi;
    }
}

// ---------------- convert idx + count ----------------
__global__ void conv_count_kernel(const void* ei) {
    int i = blockIdx.x * blockDim.x + threadIdx.x;
    if (i >= N_EDGES) return;
    int s, d;
    if (g_is64) {
        const long long* p = (const long long*)ei;
        s = (int)p[i]; d = (int)p[N_EDGES + i];
    } else {
        const int* p = (const int*)ei;
        s = p[i]; d = p[N_EDGES + i];
    }
    g_src[i] = s; g_dst[i] = d;
    atomicAdd(&g_cnt[d], 1);
}

__global__ void inv_kernel() {
    int i = blockIdx.x * blockDim.x + threadIdx.x;
    if (i < N_NODES) {
        int c = g_cnt[i];
        g_inv[i] = 1.0f / (float)(c > 1 ? c : 1);
    }
}

// ---------------- h init (+ split) ----------------
__global__ void hinit_kernel(const float* __restrict__ x, const float* __restrict__ u,
                             const float* __restrict__ Wp, const float* __restrict__ bp) {
    __shared__ float sW[H * (ND + GD)];
    __shared__ float sb[H];
    __shared__ float su[GD];
    int t = threadIdx.x;
    for (int i = t; i < H * (ND + GD); i += 256) sW[i] = Wp[i];
    if (t < H) sb[t] = bp[t];
    if (t < GD) su[t] = u[t];
    __syncthreads();
    int gid = blockIdx.x * 256 + t;
    int node = gid >> 6, o = gid & 63;
    const float* xr = x + (size_t)node * ND;
    const float* w = sW + o * (ND + GD);
    float acc = sb[o];
#pragma unroll
    for (int i = 0; i < ND; i++) acc += xr[i] * w[i];
#pragma unroll
    for (int i = 0; i < GD; i++) acc += su[i] * w[ND + i];
    float v = tanhf(acc);
    g_h0[(size_t)node * H + o] = v;
    __half hi = __float2half_rn(v);
    g_hs[(size_t)node * 128 + o] = hi;
    g_hs[(size_t)node * 128 + 64 + o] = __float2half_rn(v - __half2float(hi));
}

// ---------------- rfeat + split fused ----------------
__global__ void rfeat_kernel(const float* __restrict__ ea, const float* __restrict__ We1,
                             const float* __restrict__ be1) {
    __shared__ float sW[H * ED];
    __shared__ float sb[H];
    int t = threadIdx.x;
    for (int i = t; i < H * ED; i += 256) sW[i] = We1[i];
    if (t < H) sb[t] = be1[t];
    __syncthreads();
    int gid = blockIdx.x * 256 + t;
    int e = gid >> 6, k = gid & 63;
    const float* er = ea + (size_t)e * ED;
    float acc = sb[k];
#pragma unroll
    for (int i = 0; i < ED; i++) acc += er[i] * sW[k * ED + i];
    float v = fmaxf(acc, 0.0f);
    __half hi = __float2half_rn(v);
    g_a[(size_t)e * 128 + k] = hi;
    g_a[(size_t)e * 128 + 64 + k] = __float2half_rn(v - __half2float(hi));
}

// ---------------- mma helper ----------------
__device__ __forceinline__ void mma16816(float* c, const uint32_t* a, const uint32_t* b) {
    asm volatile(
        "mma.sync.aligned.m16n8k16.row.col.f32.f16.f16.f32 "
        "{%0,%1,%2,%3}, {%4,%5,%6,%7}, {%8,%9}, {%0,%1,%2,%3};"
        : "+f"(c[0]), "+f"(c[1]), "+f"(c[2]), "+f"(c[3])
        : "r"(a[0]), "r"(a[1]), "r"(a[2]), "r"(a[3]), "r"(b[0]), "r"(b[1]));
}

// ---------------- ew GEMM (verified) ----------------
#define GEMM_SMEM (2 * 128 * 68 * 4)

__global__ __launch_bounds__(256) void ewgemm_kernel(const float* __restrict__ be2) {
    extern __shared__ uint32_t sw[];
    uint32_t* As = sw;
    uint32_t* Bs = sw + 128 * 68;
    const int t = threadIdx.x;
    const int jb = blockIdx.x * 128;
    const int eb = blockIdx.y * 128;

    {
        int row = t >> 1, half = t & 1;
        const uint4* asrc = (const uint4*)(g_a + (size_t)(eb + row) * 128) + half * 8;
        const uint4* bsrc = (const uint4*)(g_b + (size_t)(jb + row) * 128) + half * 8;
        uint4* adst = (uint4*)(As + row * 68) + half * 8;
        uint4* bdst = (uint4*)(Bs + row * 68) + half * 8;
#pragma unroll
        for (int q = 0; q < 8; q++) { adst[q] = asrc[q]; bdst[q] = bsrc[q]; }
    }
    __syncthreads();

    const int wid = t >> 5, lane = t & 31;
    const int wm = wid & 3, wn = wid >> 2;
    const int g = lane >> 2, t4 = lane & 3;

    float acc[2][8][4];
#pragma unroll
    for (int mi = 0; mi < 2; mi++)
#pragma unroll
        for (int ni = 0; ni < 8; ni++)
#pragma unroll
            for (int q = 0; q < 4; q++) acc[mi][ni][q] = 0.0f;

    const uint32_t* Aw = As + (wm * 32 + g) * 68;
    const uint32_t* Bw = Bs + (wn * 64 + g) * 68;
#pragma unroll
    for (int ks = 0; ks < 8; ks++) {
        const int idx0 = ks * 8 + t4;
        uint32_t a[2][4], b[8][2];
#pragma unroll
        for (int mi = 0; mi < 2; mi++) {
            const uint32_t* p = Aw + mi * 16 * 68;
            a[mi][0] = p[idx0];
            a[mi][1] = p[8 * 68 + idx0];
            a[mi][2] = p[idx0 + 4];
            a[mi][3] = p[8 * 68 + idx0 + 4];
        }
#pragma unroll
        for (int ni = 0; ni < 8; ni++) {
            const uint32_t* p = Bw + ni * 8 * 68;
            b[ni][0] = p[idx0];
            b[ni][1] = p[idx0 + 4];
        }
#pragma unroll
        for (int mi = 0; mi < 2; mi++)
#pragma unroll
            for (int ni = 0; ni < 8; ni++)
                mma16816(acc[mi][ni], a[mi], b[ni]);
    }

#pragma unroll
    for (int ni = 0; ni < 8; ni++) {
        int col = jb + wn * 64 + ni * 8 + 2 * t4;
        float2 bb = *(const float2*)&be2[col];
#pragma unroll
        for (int mi = 0; mi < 2; mi++) {
            int row = eb + wm * 32 + mi * 16 + g;
            __half2 v0 = __floats2half2_rn(acc[mi][ni][0] + bb.x, acc[mi][ni][1] + bb.y);
            __half2 v1 = __floats2half2_rn(acc[mi][ni][2] + bb.x, acc[mi][ni][3] + bb.y);
            *(__half2*)(g_ewh + (size_t)row * 4096 + col) = v0;
            *(__half2*)(g_ewh + (size_t)(row + 8) * 4096 + col) = v1;
        }
    }
}

// ---------------- per step: msg + scatter-add ----------------
__global__ __launch_bounds__(512) void msg_kernel(int parity) {
    const float* hin = parity ? g_h1 : g_h0;
    __shared__ float sh[16][64];
    int w = threadIdx.x >> 5, l = threadIdx.x & 31;
    int e = blockIdx.x * 16 + w;
    int s = g_src[e], d = g_dst[e];
    sh[w][l] = hin[(size_t)s * H + l];
    sh[w][l + 32] = hin[(size_t)s * H + l + 32];
    __syncwarp();
    float a0 = 0.0f, a1 = 0.0f;
    const __half2* row = (const __half2*)(g_ewh + (size_t)e * 4096) + l;
#pragma unroll 16
    for (int hh = 0; hh < 64; hh++) {
        float hv = sh[w][hh];
        float2 v = __half22float2(row[hh * 32]);
        a0 += hv * v.x;
        a1 += hv * v.y;
    }
    atomicAdd(&g_agg[(size_t)d * H + 2 * l], a0);
    atomicAdd(&g_agg[(size_t)d * H + 2 * l + 1], a1);
}

// ---------------- per step: fully-fused tensor GRU ----------------
// smem layout (u32 offsets), 512 threads, 128 nodes/block:
//   phase1 : As @0 (128*68=8704) | Bs1 @8704 (256*68=17408)        [0..26112)
//   phase2 : s_gh  @0     stride 196 (128 rows x 192 cols)         [0..25088)
//            s_hroot @25088 stride 68 (128 x 64)                   [25088..33792)
//            Bs2 @33792 (192*68=13056)                             [33792..46848)
//            Am  @46848 (128*68=8704)                              [46848..55552)
//   phase3 : s_gi @25088 stride 196 (128 x 192)                    [25088..50176)
//   bias   : @55552 (448) [bih 192 | bhh 192 | cb 64]              [55552..56000)
#define GRU_SMEM (56000 * 4)   // 224000 bytes

__device__ __forceinline__ float sigf(float x) { return 1.0f / (1.0f + expf(-x)); }

__global__ __launch_bounds__(512) void gru_fused_kernel(int parity,
        const float* __restrict__ bih, const float* __restrict__ bhh,
        const float* __restrict__ conv_b) {
    const float* hin = parity ? g_h1 : g_h0;
    float* hout = parity ? g_h0 : g_h1;
    extern __shared__ uint32_t sw[];
    uint32_t* As    = sw;
    uint32_t* Bs1   = sw + 8704;
    float* s_gh     = (float*)sw;            // stride 196
    float* s_hroot  = (float*)(sw + 25088);  // stride 68
    uint32_t* Bs2   = sw + 33792;
    uint32_t* Am    = sw + 46848;
    float* s_gi     = (float*)(sw + 25088);  // stride 196, phase 3
    float* s_bias   = (float*)(sw + 55552);

    const int t = threadIdx.x;
    const int eb = blockIdx.x * 128;
    const int wid = t >> 5, lane = t & 31;
    const int wm = wid & 3, wn = wid >> 2;       // 4 x 4 warp grid
    const int g = lane >> 2, t4 = lane & 3;

    if (t < 192) { s_bias[t] = bih[t]; s_bias[192 + t] = bhh[t]; }
    if (t >= 192 && t < 256) s_bias[384 + (t - 192)] = conv_b[t - 192];

    // ---- phase 1 staging (full rows: 16 uint4 each) ----
    for (int i = t; i < 128 * 16; i += 512) {
        int row = i >> 4, q = i & 15;
        ((uint4*)(As + row * 68))[q] = ((const uint4*)(g_hs + (size_t)(eb + row) * 128))[q];
    }
    for (int i = t; i < 256 * 16; i += 512) {
        int row = i >> 4, q = i & 15;
        ((uint4*)(Bs1 + row * 68))[q] = ((const uint4*)(g_gB1 + (size_t)row * 128))[q];
    }
    __syncthreads();

    // ---- GEMM1: h(128 x 128h) @ B1(256 x 128h)^T -> [gh | hroot] ----
    float acc[2][8][4];
#pragma unroll
    for (int mi = 0; mi < 2; mi++)
#pragma unroll
        for (int ni = 0; ni < 8; ni++)
#pragma unroll
            for (int q = 0; q < 4; q++) acc[mi][ni][q] = 0.0f;
    {
        const uint32_t* Aw = As + (wm * 32 + g) * 68;
        const uint32_t* Bw = Bs1 + (wn * 64 + g) * 68;
#pragma unroll
        for (int ks = 0; ks < 8; ks++) {
            const int idx0 = ks * 8 + t4;
            uint32_t a[2][4], b[8][2];
#pragma unroll
            for (int mi = 0; mi < 2; mi++) {
                const uint32_t* p = Aw + mi * 16 * 68;
                a[mi][0] = p[idx0];
                a[mi][1] = p[8 * 68 + idx0];
                a[mi][2] = p[idx0 + 4];
                a[mi][3] = p[8 * 68 + idx0 + 4];
            }
#pragma unroll
            for (int ni = 0; ni < 8; ni++) {
                const uint32_t* p = Bw + ni * 8 * 68;
                b[ni][0] = p[idx0];
                b[ni][1] = p[idx0 + 4];
            }
#pragma unroll
            for (int mi = 0; mi < 2; mi++)
#pragma unroll
                for (int ni = 0; ni < 8; ni++)
                    mma16816(acc[mi][ni], a[mi], b[ni]);
        }
    }
    __syncthreads();   // As/Bs1 reads done; s_gh/s_hroot overwrite them

    // epilogue: wn<3 -> gh (cols 0..191, stride 196); wn==3 -> hroot (stride 68)
#pragma unroll
    for (int ni = 0; ni < 8; ni++) {
        int col = wn * 64 + ni * 8 + 2 * t4;
#pragma unroll
        for (int mi = 0; mi < 2; mi++) {
            int row = wm * 32 + mi * 16 + g;
            if (wn < 3) {
                *(float2*)(s_gh + row * 196 + col) = make_float2(acc[mi][ni][0], acc[mi][ni][1]);
                *(float2*)(s_gh + (row + 8) * 196 + col) = make_float2(acc[mi][ni][2], acc[mi][ni][3]);
            } else {
                int hc = col - 192;
                *(float2*)(s_hroot + row * 68 + hc) = make_float2(acc[mi][ni][0], acc[mi][ni][1]);
                *(float2*)(s_hroot + (row + 8) * 68 + hc) = make_float2(acc[mi][ni][2], acc[mi][ni][3]);
            }
        }
    }
    __syncthreads();

    // ---- phase 2 staging: B2 (192 x 16 uint4), A_m from agg/hroot/cb (+reset agg) ----
    for (int i = t; i < 192 * 16; i += 512) {
        int row = i >> 4, q = i & 15;
        ((uint4*)(Bs2 + row * 68))[q] = ((const uint4*)(g_gB2 + (size_t)row * 128))[q];
    }
    {
        int r = t >> 2, q4 = t & 3;
        int node = eb + r;
        float ic = g_inv[node];
        float* aggp = g_agg + (size_t)node * 64;
        const float* ghr = s_hroot + r * 68;
#pragma unroll
        for (int q = 0; q < 4; q++) {
            int c = q4 * 16 + q * 4;
            float4 ag = *(float4*)(aggp + c);
            float4 hr = *(const float4*)(ghr + c);
            float4 cb4 = *(const float4*)(s_bias + 384 + c);
            *(float4*)(aggp + c) = make_float4(0.f, 0.f, 0.f, 0.f);
            float m0 = fmaxf(ag.x * ic + hr.x + cb4.x, 0.f);
            float m1 = fmaxf(ag.y * ic + hr.y + cb4.y, 0.f);
            float m2 = fmaxf(ag.z * ic + hr.z + cb4.z, 0.f);
            float m3 = fmaxf(ag.w * ic + hr.w + cb4.w, 0.f);
            __half h0 = __float2half_rn(m0), h1 = __float2half_rn(m1);
            __half h2 = __float2half_rn(m2), h3 = __float2half_rn(m3);
            __half2 hi01 = __halves2half2(h0, h1), hi23 = __halves2half2(h2, h3);
            __half2 lo01 = __halves2half2(__float2half_rn(m0 - __half2float(h0)),
                                          __float2half_rn(m1 - __half2float(h1)));
            __half2 lo23 = __halves2half2(__float2half_rn(m2 - __half2float(h2)),
                                          __float2half_rn(m3 - __half2float(h3)));
            Am[r * 68 + c / 2]          = *(uint32_t*)&hi01;
            Am[r * 68 + c / 2 + 1]      = *(uint32_t*)&hi23;
            Am[r * 68 + 32 + c / 2]     = *(uint32_t*)&lo01;
            Am[r * 68 + 32 + c / 2 + 1] = *(uint32_t*)&lo23;
        }
    }
    __syncthreads();

    // ---- GEMM2: m(128 x 128h) @ B2(192 x 128h)^T -> gi (128 x 192) ----
    float acc2[2][6][4];
#pragma unroll
    for (int mi = 0; mi < 2; mi++)
#pragma unroll
        for (int ni = 0; ni < 6; ni++)
#pragma unroll
            for (int q = 0; q < 4; q++) acc2[mi][ni][q] = 0.0f;
    {
        const uint32_t* Aw = Am + (wm * 32 + g) * 68;
        const uint32_t* Bw = Bs2 + (wn * 48 + g) * 68;
#pragma unroll
        for (int ks = 0; ks < 8; ks++) {
            const int idx0 = ks * 8 + t4;
            uint32_t a[2][4], b[6][2];
#pragma unroll
            for (int mi = 0; mi < 2; mi++) {
                const uint32_t* p = Aw + mi * 16 * 68;
                a[mi][0] = p[idx0];
                a[mi][1] = p[8 * 68 + idx0];
                a[mi][2] = p[idx0 + 4];
                a[mi][3] = p[8 * 68 + idx0 + 4];
            }
#pragma unroll
            for (int ni = 0; ni < 6; ni++) {
                const uint32_t* p = Bw + ni * 8 * 68;
                b[ni][0] = p[idx0];
                b[ni][1] = p[idx0 + 4];
            }
#pragma unroll
            for (int mi = 0; mi < 2; mi++)
#pragma unroll
                for (int ni = 0; ni < 6; ni++)
                    mma16816(acc2[mi][ni], a[mi], b[ni]);
        }
    }
    __syncthreads();   // Bs2/Am/hroot dead; s_gi overwrites [25088..50176)

#pragma unroll
    for (int ni = 0; ni < 6; ni++) {
        int col = wn * 48 + ni * 8 + 2 * t4;
#pragma unroll
        for (int mi = 0; mi < 2; mi++) {
            int row = wm * 32 + mi * 16 + g;
            *(float2*)(s_gi + row * 196 + col) = make_float2(acc2[mi][ni][0], acc2[mi][ni][1]);
            *(float2*)(s_gi + (row + 8) * 196 + col) = make_float2(acc2[mi][ni][2], acc2[mi][ni][3]);
        }
    }
    __syncthreads();

    // ---- gates ----
    {
        int r = t >> 2, q4 = t & 3;
        int node = eb + r;
        const float* girow = s_gi + r * 196;
        const float* ghrow = s_gh + r * 196;
#pragma unroll
        for (int q = 0; q < 4; q++) {
            int c = q4 * 16 + q * 4;
            float4 gir = *(const float4*)(girow + c);
            float4 giz = *(const float4*)(girow + 64 + c);
            float4 gin = *(const float4*)(girow + 128 + c);
            float4 ghr = *(const float4*)(ghrow + c);
            float4 ghz = *(const float4*)(ghrow + 64 + c);
            float4 ghn = *(const float4*)(ghrow + 128 + c);
            float4 hv  = *(const float4*)(hin + (size_t)node * 64 + c);
            float4 bir = *(const float4*)(s_bias + c);
            float4 biz = *(const float4*)(s_bias + 64 + c);
            float4 bin = *(const float4*)(s_bias + 128 + c);
            float4 bhr = *(const float4*)(s_bias + 192 + c);
            float4 bhz = *(const float4*)(s_bias + 256 + c);
            float4 bhn = *(const float4*)(s_bias + 320 + c);
            float gr[4] = {gir.x + bir.x + ghr.x + bhr.x, gir.y + bir.y + ghr.y + bhr.y,
                           gir.z + bir.z + ghr.z + bhr.z, gir.w + bir.w + ghr.w + bhr.w};
            float gz[4] = {giz.x + biz.x + ghz.x + bhz.x, giz.y + biz.y + ghz.y + bhz.y,
                           giz.z + biz.z + ghz.z + bhz.z, giz.w + biz.w + ghz.w + bhz.w};
            float gni[4] = {gin.x + bin.x, gin.y + bin.y, gin.z + bin.z, gin.w + bin.w};
            float gnh[4] = {ghn.x + bhn.x, ghn.y + bhn.y, ghn.z + bhn.z, ghn.w + bhn.w};
            float hvv[4] = {hv.x, hv.y, hv.z, hv.w};
            float o_[4], lo_[4];
#pragma unroll
            for (int j = 0; j < 4; j++) {
                float rr = sigf(gr[j]);
                float zz = sigf(gz[j]);
                float nn = tanhf(gni[j] + rr * gnh[j]);
                o_[j] = (1.0f - zz) * nn + zz * hvv[j];
                __half hh = __float2half_rn(o_[j]);
                lo_[j] = o_[j] - __half2float(hh);
            }
            *(float4*)(hout + (size_t)node * 64 + c) = make_float4(o_[0], o_[1], o_[2], o_[3]);
            __half2* hsp = (__half2*)(g_hs + (size_t)node * 128 + c);
            hsp[0] = __floats2half2_rn(o_[0], o_[1]);
            hsp[1] = __floats2half2_rn(o_[2], o_[3]);
            __half2* lsp = (__half2*)(g_hs + (size_t)node * 128 + 64 + c);
            lsp[0] = __floats2half2_rn(lo_[0], lo_[1]);
            lsp[1] = __floats2half2_rn(lo_[2], lo_[3]);
        }
    }
}

// ---------------- decoder ----------------
__global__ __launch_bounds__(256) void decoder_kernel(int parity,
        const float* __restrict__ ea,
        const float* __restrict__ bd1, const float* __restrict__ bd2,
        const float* __restrict__ Wd3, const float* __restrict__ bd3,
        float* __restrict__ out) {
    const float* hin = parity ? g_h1 : g_h0;
    extern __shared__ float sm[];
    float* s_w1 = sm;
    float* s_w2 = s_w1 + 133 * 64;
    float* s_w3 = s_w2 + 64 * 32;
    float* s_b1 = s_w3 + 128;
    float* s_b2 = s_b1 + 64;
    float* s_b3 = s_b2 + 32;
    float* s_in = s_b3 + 4;
    float* s_d1 = s_in + 8 * 136;
    float* s_d2 = s_d1 + 8 * 64;

    int t = threadIdx.x;
    for (int i = t; i < 133 * 64; i += 256) s_w1[i] = g_w1T[i];
    for (int i = t; i < 64 * 32; i += 256) s_w2[i] = g_w2T[i];
    if (t < 128) s_w3[t] = Wd3[t];
    if (t < 64) s_b1[t] = bd1[t];
    if (t < 32) s_b2[t] = bd2[t];
    if (t < 4)  s_b3[t] = bd3[t];
    __syncthreads();

    int w = t >> 5, l = t & 31;

    for (int it = 0; it < 8; it++) {
        int e = blockIdx.x * 64 + it * 8 + w;
        int s = g_src[e], d = g_dst[e];
        s_in[w * 136 + l]      = hin[(size_t)s * H + l];
        s_in[w * 136 + l + 32] = hin[(size_t)s * H + l + 32];
        s_in[w * 136 + 64 + l]      = hin[(size_t)d * H + l];
        s_in[w * 136 + 64 + l + 32] = hin[(size_t)d * H + l + 32];
        if (l < ED) s_in[w * 136 + 128 + l] = ea[(size_t)e * ED + l];
        __syncwarp();

        float a0 = s_b1[l], a1 = s_b1[l + 32];
        for (int i = 0; i < 133; i++) {
            float v = s_in[w * 136 + i];
            a0 += v * s_w1[i * 64 + l];
            a1 += v * s_w1[i * 64 + l + 32];
        }
        s_d1[w * 64 + l] = fmaxf(a0, 0.0f);
        s_d1[w * 64 + l + 32] = fmaxf(a1, 0.0f);
        __syncwarp();

        float a2 = s_b2[l];
        for (int o = 0; o < 64; o++) a2 += s_d1[w * 64 + o] * s_w2[o * 32 + l];
        s_d2[w * 32 + l] = fmaxf(a2, 0.0f);
        __syncwarp();

        if (l < T_OUT) {
            float a3 = s_b3[l];
            for (int j = 0; j < 32; j++) a3 += s_d2[w * 32 + j] * s_w3[l * 32 + j];
            out[(size_t)e * T_OUT + l] = a3;
        }
        __syncwarp();
    }
}

#define DEC_SMEM  ((133*64 + 64*32 + 128 + 64 + 32 + 4 + 8*136 + 8*64 + 8*32) * 4)

static void set_attrs() {
    cudaFuncSetAttribute(ewgemm_kernel, cudaFuncAttributeMaxDynamicSharedMemorySize, GEMM_SMEM);
    cudaFuncSetAttribute(gru_fused_kernel, cudaFuncAttributeMaxDynamicSharedMemorySize, GRU_SMEM);
    cudaFuncSetAttribute(decoder_kernel, cudaFuncAttributeMaxDynamicSharedMemorySize, DEC_SMEM);
}

namespace { struct WarmLoad { WarmLoad() { set_attrs(); } } s_warm; }

extern "C" void kernel_launch(void* const* d_in, const int* in_sizes, int n_in,
                              void* d_out, int out_size) {
    (void)in_sizes; (void)n_in; (void)out_size;
    const float* x   = (const float*)d_in[0];
    const void*  ei  = d_in[1];
    const float* ea  = (const float*)d_in[2];
    const float* u   = (const float*)d_in[3];
    const float* Wp  = (const float*)d_in[4];
    const float* bp  = (const float*)d_in[5];
    const float* We1 = (const float*)d_in[6];
    const float* be1 = (const float*)d_in[7];
    const float* We2 = (const float*)d_in[8];
    const float* be2 = (const float*)d_in[9];
    const float* root = (const float*)d_in[10];
    const float* cb   = (const float*)d_in[11];
    const float* Wih = (const float*)d_in[12];
    const float* bih = (const float*)d_in[13];
    const float* Whh = (const float*)d_in[14];
    const float* bhh = (const float*)d_in[15];
    const float* Wd1 = (const float*)d_in[16];
    const float* bd1 = (const float*)d_in[17];
    const float* Wd2 = (const float*)d_in[18];
    const float* bd2 = (const float*)d_in[19];
    const float* Wd3 = (const float*)d_in[20];
    const float* bd3 = (const float*)d_in[21];
    float* out = (float*)d_out;

    set_attrs();

    init_kernel<<<N_NODES * H / 4 / 256, 256>>>((const long long*)ei, Whh, root, Wih, Wd1, Wd2, We2);
    conv_count_kernel<<<N_EDGES / 256, 256>>>(ei);
    inv_kernel<<<N_NODES / 256, 256>>>();
    hinit_kernel<<<N_NODES * H / 256, 256>>>(x, u, Wp, bp);
    rfeat_kernel<<<N_EDGES * H / 256, 256>>>(ea, We1, be1);

    {
        dim3 grid(4096 / 128, N_EDGES / 128);
        ewgemm_kernel<<<grid, 256, GEMM_SMEM>>>(be2);
    }

    for (int s = 0; s < STEPS; s++) {
        int parity = s & 1;
        msg_kernel<<<N_EDGES / 16, 512>>>(parity);
        gru_fused_kernel<<<N_NODES / 128, 512, GRU_SMEM>>>(parity, bih, bhh, cb);
    }

    decoder_kernel<<<N_EDGES / 64, 256, DEC_SMEM>>>(1, ea, bd1, bd2, Wd3, bd3, out);
}